// round 16
// baseline (speedup 1.0000x reference)
#include <cuda_runtime.h>

#define NN_MAX 100000
#define EE_MAX 1600000
#define D 64
#define EPSV 1e-12f
#define NB 128           // build-kernel blocks (must all be wave-1 resident)
#define BT 1024          // build-kernel threads per block

// Scratch (no allocations allowed)
__device__ float g_invn[NN_MAX];        // 1/max(||feat_row||, eps)
__device__ int   g_hist[NN_MAX];        // in-degree (zero-on-entry invariant)
__device__ int   g_rank[EE_MAX];        // edge rank within its dst bucket
__device__ int   g_rowptr[NN_MAX + 1];  // CSR row pointers (by dst)
__device__ int   g_bsums[NB];           // scan block totals
__device__ int   g_barrier[3];          // grid-barrier counters (agg resets)
__device__ int   g_esrc[EE_MAX];        // src ids grouped by dst

// warp-shuffle inclusive scan helper
__device__ __forceinline__ int warp_iscan(int x, int lane) {
    #pragma unroll
    for (int o = 1; o < 32; o <<= 1) {
        int t = __shfl_up_sync(0xffffffffu, x, o);
        if (lane >= o) x += t;
    }
    return x;
}

// resident-grid counter barrier (all NB blocks wave-1 resident)
__device__ __forceinline__ void grid_barrier(int idx) {
    __syncthreads();
    if (threadIdx.x == 0) {
        __threadfence();
        atomicAdd(&g_barrier[idx], 1);
        while (atomicAdd(&g_barrier[idx], 0) < NB) {}
    }
    __syncthreads();
}

// ---------------------------------------------------------------------------
// BUILD: norm + hist/rank | scan | rowptr | scatter — one kernel, 3 barriers.
// g_hist zero on entry (module load / re-zeroed in scan phase each replay).
// g_barrier zero on entry (module load / reset by k_agg each replay).
__global__ void __launch_bounds__(BT, 1)
k_build(const float* __restrict__ feat,
        const int* __restrict__ src,
        const int* __restrict__ dst,
        int n_nodes, int n_edges) {
    __shared__ int wsum[32];
    __shared__ int s_off;
    int tid  = threadIdx.x;
    int lane = tid & 31;
    int wid  = tid >> 5;
    int t    = blockIdx.x * BT + tid;
    int stride = NB * BT;

    // ---- phase 1a: per-row inverse L2 norm (warp per row, grid-stride) ----
    int gw = t >> 5;
    for (int row = gw; row < n_nodes; row += stride >> 5) {
        float2 v = reinterpret_cast<const float2*>(feat + (size_t)row * D)[lane];
        float s = v.x * v.x + v.y * v.y;
        #pragma unroll
        for (int o = 16; o; o >>= 1) s += __shfl_xor_sync(0xffffffffu, s, o);
        if (lane == 0) g_invn[row] = 1.0f / fmaxf(sqrtf(s), EPSV);
    }

    // ---- phase 1b: in-degree histogram + per-edge rank ----
    for (int i = t; i < n_edges; i += stride)
        g_rank[i] = atomicAdd(&g_hist[dst[i]], 1);

    grid_barrier(0);

    // ---- phase 2: block-local exclusive scan of hist chunk ----
    int ch   = (n_nodes + NB - 1) / NB;           // <= BT (100000/128 = 782)
    int i    = blockIdx.x * ch + tid;
    bool inr = (tid < ch) && (i < n_nodes);
    int v = inr ? g_hist[i] : 0;
    if (inr) g_hist[i] = 0;                        // restore invariant
    int x = warp_iscan(v, lane);
    if (lane == 31) wsum[wid] = x;
    __syncthreads();
    if (wid == 0) wsum[lane] = warp_iscan(wsum[lane], lane);
    __syncthreads();
    int excl = (wid ? wsum[wid - 1] : 0) + x - v;  // block-local exclusive
    int total = wsum[31];
    if (tid == 0) g_bsums[blockIdx.x] = total;

    grid_barrier(1);

    // ---- phase 3: cross-block offset, write global rowptr ----
    int bv = (tid < (int)blockIdx.x) ? g_bsums[tid] : 0;
    #pragma unroll
    for (int o = 16; o; o >>= 1) bv += __shfl_xor_sync(0xffffffffu, bv, o);
    __syncthreads();                               // wsum reuse barrier
    if (lane == 0) wsum[wid] = bv;
    __syncthreads();
    if (wid == 0) {
        int r = wsum[lane];
        #pragma unroll
        for (int o = 16; o; o >>= 1) r += __shfl_xor_sync(0xffffffffu, r, o);
        if (lane == 0) s_off = r;
    }
    __syncthreads();
    if (inr) g_rowptr[i] = excl + s_off;
    if (blockIdx.x == 0 && tid == 0) g_rowptr[n_nodes] = n_edges;

    grid_barrier(2);

    // ---- phase 4: atomic-free scatter (4 edges per thread per pass) ----
    for (int base = t; base < n_edges; base += stride * 4) {
        int d[4], s[4], r[4];
        bool vv[4];
        #pragma unroll
        for (int k = 0; k < 4; k++) {
            int e = base + k * stride;
            vv[k] = (e < n_edges);
            d[k] = vv[k] ? dst[e] : 0;
            s[k] = vv[k] ? src[e] : 0;
            r[k] = vv[k] ? g_rank[e] : 0;
        }
        int p[4];
        #pragma unroll
        for (int k = 0; k < 4; k++)
            p[k] = g_rowptr[d[k]] + r[k];
        #pragma unroll
        for (int k = 0; k < 4; k++)
            if (vv[k]) g_esrc[p[k]] = s[k];
    }
}

// ---------------------------------------------------------------------------
// AGG (exact R14): warp per dst, 8 lanes per edge (4 edges per warp-iter),
// two-depth pipeline (index at depth 2, row data at depth 1).
// Also resets the build kernel's barrier counters for the next replay
// (stream-ordered: build has fully consumed them before agg runs).
__global__ void k_agg(const float* __restrict__ feat,
                      const float* __restrict__ beta,
                      float* __restrict__ out, int n_nodes) {
    if (blockIdx.x == 0 && threadIdx.x < 3) g_barrier[threadIdx.x] = 0;

    int w    = (blockIdx.x * blockDim.x + threadIdx.x) >> 5;
    int lane = threadIdx.x & 31;
    if (w >= n_nodes) return;
    int grp = lane >> 3;       // which edge of the quad (0..3)
    int g   = lane & 7;        // lane within group

    const float4* feat4 = reinterpret_cast<const float4*>(feat);
    float4 fda = feat4[(size_t)w * 16 + g];
    float4 fdb = feat4[(size_t)w * 16 + g + 8];
    float bscale = beta[0] * g_invn[w];     // TEMP == 1
    int beg = g_rowptr[w], end = g_rowptr[w + 1];
    int deg = end - beg;
    int nfull = deg >> 2;                   // full quads, no predication
    int rem   = deg & 3;

    float denom = 0.0f;
    float4 A = make_float4(0.f, 0.f, 0.f, 0.f);
    float4 B = make_float4(0.f, 0.f, 0.f, 0.f);

    // prologue: index for quad 0 and quad 1; row data for quad 0
    int s_cur = (nfull > 0) ? g_esrc[beg + grp] : 0;
    int s_nx  = (nfull > 1) ? g_esrc[beg + 4 + grp] : 0;
    float4 a_n, b_n;
    float  iv_n = 0.0f;
    if (nfull > 0) {
        iv_n = g_invn[s_cur];
        const float4* rp = feat4 + (size_t)s_cur * 16;
        a_n = rp[g];
        b_n = rp[g + 8];
    }

    for (int it = 0; it < nfull; it++) {
        float4 a = a_n, b = b_n;
        float  iv = iv_n;
        s_cur = s_nx;                           // index for it+1 (arrived)
        if (it + 2 < nfull)                     // index prefetch, depth 2
            s_nx = g_esrc[beg + (it + 2) * 4 + grp];
        if (it + 1 < nfull) {                   // row prefetch, depth 1
            iv_n = g_invn[s_cur];
            const float4* rp = feat4 + (size_t)s_cur * 16;
            a_n = rp[g];
            b_n = rp[g + 8];
        }
        float p = a.x * fda.x + a.y * fda.y + a.z * fda.z + a.w * fda.w
                + b.x * fdb.x + b.y * fdb.y + b.z * fdb.z + b.w * fdb.w;
        p += __shfl_xor_sync(0xffffffffu, p, 4);
        p += __shfl_xor_sync(0xffffffffu, p, 2);
        p += __shfl_xor_sync(0xffffffffu, p, 1);
        float ex = __expf(bscale * iv * p);
        denom += ex;
        A.x += ex * a.x; A.y += ex * a.y; A.z += ex * a.z; A.w += ex * a.w;
        B.x += ex * b.x; B.y += ex * b.y; B.z += ex * b.z; B.w += ex * b.w;
    }
    if (rem) {                              // tail quad, predicated once
        int e = beg + nfull * 4 + grp;
        bool valid = (grp < rem);
        int s = valid ? g_esrc[e] : 0;
        float iv = g_invn[s];
        const float4* rp = feat4 + (size_t)s * 16;
        float4 a = rp[g];
        float4 b = rp[g + 8];
        float p = a.x * fda.x + a.y * fda.y + a.z * fda.z + a.w * fda.w
                + b.x * fdb.x + b.y * fdb.y + b.z * fdb.z + b.w * fdb.w;
        p += __shfl_xor_sync(0xffffffffu, p, 4);
        p += __shfl_xor_sync(0xffffffffu, p, 2);
        p += __shfl_xor_sync(0xffffffffu, p, 1);
        float ex = valid ? __expf(bscale * iv * p) : 0.0f;
        denom += ex;
        A.x += ex * a.x; A.y += ex * a.y; A.z += ex * a.z; A.w += ex * a.w;
        B.x += ex * b.x; B.y += ex * b.y; B.z += ex * b.z; B.w += ex * b.w;
    }

    // combine the 4 edge-groups (lane g in each group owns the same dims)
    #pragma unroll
    for (int o = 8; o <= 16; o <<= 1) {
        denom += __shfl_xor_sync(0xffffffffu, denom, o);
        A.x += __shfl_xor_sync(0xffffffffu, A.x, o);
        A.y += __shfl_xor_sync(0xffffffffu, A.y, o);
        A.z += __shfl_xor_sync(0xffffffffu, A.z, o);
        A.w += __shfl_xor_sync(0xffffffffu, A.w, o);
        B.x += __shfl_xor_sync(0xffffffffu, B.x, o);
        B.y += __shfl_xor_sync(0xffffffffu, B.y, o);
        B.z += __shfl_xor_sync(0xffffffffu, B.z, o);
        B.w += __shfl_xor_sync(0xffffffffu, B.w, o);
    }

    if (lane < 8) {
        float r = 1.0f / fmaxf(denom, EPSV);
        float4 o1 = make_float4(A.x * r, A.y * r, A.z * r, A.w * r);
        float4 o2 = make_float4(B.x * r, B.y * r, B.z * r, B.w * r);
        float4* out4 = reinterpret_cast<float4*>(out);
        out4[(size_t)w * 16 + g]     = o1;
        out4[(size_t)w * 16 + g + 8] = o2;
    }
}

// ---------------------------------------------------------------------------
extern "C" void kernel_launch(void* const* d_in, const int* in_sizes, int n_in,
                              void* d_out, int out_size) {
    const float* feat = (const float*)d_in[0];
    const float* beta = (const float*)d_in[1];
    const int*   src  = (const int*)d_in[2];   // JAX default int32 (no x64)
    const int*   dst  = (const int*)d_in[3];
    float*       out  = (float*)d_out;

    int n_nodes = in_sizes[0] / D;
    int n_edges = in_sizes[2];
    if (n_nodes > NN_MAX) n_nodes = NN_MAX;
    if (n_edges > EE_MAX) n_edges = EE_MAX;

    int roww_blocks = (n_nodes + 7) / 8;          // warp-per-dst for agg

    k_build<<<NB, BT>>>(feat, src, dst, n_nodes, n_edges);
    k_agg  <<<roww_blocks, 256>>>(feat, beta, out, n_nodes);
}

// round 17
// speedup vs baseline: 1.0473x; 1.0473x over previous
#include <cuda_runtime.h>
#include <cuda_fp16.h>

#define NN_MAX 100000
#define EE_MAX 1600000
#define D 64
#define EPSV 1e-12f
#define SCAN_B 1024

// Scratch (no allocations allowed)
__device__ float   g_invn[NN_MAX];        // 1/max(||feat_row||, eps)
__device__ int     g_hist[NN_MAX];        // in-degree (zero-on-entry invariant)
__device__ int     g_rank[EE_MAX];        // edge rank within its dst bucket
__device__ int     g_rowptr[NN_MAX + 1];  // CSR row pointers (by dst)
__device__ int     g_bsums[128];          // scan block totals
__device__ int     g_ready[128];          // scan publish flags (zeroed by A)
__device__ int     g_esrc[EE_MAX];        // src ids grouped by dst
__device__ __half2 g_feat16[NN_MAX * 32]; // fp16 mirror of feat (row = 32 h2)

// ---------------------------------------------------------------------------
// A: per-row inverse L2 norm + fp16 feat mirror (warp per row)
//    + hist/rank (edge grid-stride) + zero scan flags.
__global__ void k_norm_hist(const float* __restrict__ feat,
                            const int* __restrict__ dst,
                            int n_nodes, int n_edges) {
    int t    = blockIdx.x * blockDim.x + threadIdx.x;
    int w    = t >> 5;
    int lane = threadIdx.x & 31;

    if (t < 128) g_ready[t] = 0;

    if (w < n_nodes) {
        float2 v = reinterpret_cast<const float2*>(feat + (size_t)w * D)[lane];
        g_feat16[(size_t)w * 32 + lane] = __floats2half2_rn(v.x, v.y);
        float s = v.x * v.x + v.y * v.y;
        #pragma unroll
        for (int o = 16; o; o >>= 1) s += __shfl_xor_sync(0xffffffffu, s, o);
        if (lane == 0) g_invn[w] = 1.0f / fmaxf(sqrtf(s), EPSV);
    }

    int stride = gridDim.x * blockDim.x;
    for (int i = t; i < n_edges; i += stride)
        g_rank[i] = atomicAdd(&g_hist[dst[i]], 1);   // rank within bucket
}

// warp-shuffle inclusive scan helper
__device__ __forceinline__ int warp_iscan(int x, int lane) {
    #pragma unroll
    for (int o = 1; o < 32; o <<= 1) {
        int t = __shfl_up_sync(0xffffffffu, x, o);
        if (lane >= o) x += t;
    }
    return x;
}

// B: single-launch scan (<=128 resident blocks, flag-poll barrier).
// Re-zeroes g_hist (zero-on-entry invariant).
__global__ void k_scan(int n_nodes, int n_edges) {
    __shared__ int wsum[32];
    __shared__ int s_off;
    int i    = blockIdx.x * SCAN_B + threadIdx.x;
    int lane = threadIdx.x & 31;
    int wid  = threadIdx.x >> 5;

    int v = (i < n_nodes) ? g_hist[i] : 0;
    if (i < n_nodes) g_hist[i] = 0;                  // restore invariant
    int x = warp_iscan(v, lane);
    if (lane == 31) wsum[wid] = x;
    __syncthreads();
    if (wid == 0) wsum[lane] = warp_iscan(wsum[lane], lane);
    __syncthreads();
    int off_local = wid ? wsum[wid - 1] : 0;
    int block_total = wsum[31];

    if (threadIdx.x == 0) {
        g_bsums[blockIdx.x] = block_total;
        __threadfence();
        atomicExch(&g_ready[blockIdx.x], 1);
    }

    int bv = 0;
    if ((int)threadIdx.x < (int)blockIdx.x) {
        while (atomicAdd(&g_ready[threadIdx.x], 0) == 0) {}
        __threadfence();
        bv = g_bsums[threadIdx.x];
    }
    #pragma unroll
    for (int o = 16; o; o >>= 1) bv += __shfl_xor_sync(0xffffffffu, bv, o);
    __syncthreads();                 // wsum reuse barrier
    if (lane == 0) wsum[wid] = bv;
    __syncthreads();
    if (wid == 0) {
        int r = wsum[lane];
        #pragma unroll
        for (int o = 16; o; o >>= 1) r += __shfl_xor_sync(0xffffffffu, r, o);
        if (lane == 0) s_off = r;
    }
    __syncthreads();

    if (i < n_nodes) g_rowptr[i] = off_local + x - v + s_off;
    if (i == 0) g_rowptr[n_nodes] = n_edges;
}

// C: atomic-free scatter: pos = rowptr[dst] + rank (4 edges/thread)
__global__ void k_scatter(const int* __restrict__ src,
                          const int* __restrict__ dst, int n_edges) {
    int base = blockIdx.x * (blockDim.x * 4) + threadIdx.x;
    int d[4], s[4], r[4];
    bool v[4];
    #pragma unroll
    for (int k = 0; k < 4; k++) {
        int i = base + k * blockDim.x;
        v[k] = (i < n_edges);
        d[k] = v[k] ? dst[i] : 0;
        s[k] = v[k] ? src[i] : 0;
        r[k] = v[k] ? g_rank[i] : 0;
    }
    int p[4];
    #pragma unroll
    for (int k = 0; k < 4; k++)
        p[k] = g_rowptr[d[k]] + r[k];
    #pragma unroll
    for (int k = 0; k < 4; k++)
        if (v[k]) g_esrc[p[k]] = s[k];
}

// ---------------------------------------------------------------------------
// D: fused softmax + aggregation. Warp per dst, 8 lanes per edge (4 edges per
// warp-iter), two-depth pipeline. Src rows gathered in FP16: one uint4 per
// lane covers 8 dims -> one 128B line per row, halving gather bytes and
// L1tex wavefronts. All accumulation fp32.
__global__ void k_agg(const float* __restrict__ feat,
                      const float* __restrict__ beta,
                      float* __restrict__ out, int n_nodes) {
    int w    = (blockIdx.x * blockDim.x + threadIdx.x) >> 5;
    int lane = threadIdx.x & 31;
    if (w >= n_nodes) return;
    int grp = lane >> 3;       // which edge of the quad (0..3)
    int g   = lane & 7;        // lane within group

    // dst row (fp32): lane owns dims [8g, 8g+8)
    const float4* feat4 = reinterpret_cast<const float4*>(feat);
    float4 fd0 = feat4[(size_t)w * 16 + 2 * g];
    float4 fd1 = feat4[(size_t)w * 16 + 2 * g + 1];
    float bscale = beta[0] * g_invn[w];     // TEMP == 1
    int beg = g_rowptr[w], end = g_rowptr[w + 1];
    int deg = end - beg;
    int nfull = deg >> 2;                   // full quads, no predication
    int rem   = deg & 3;

    const uint4* feat16 = reinterpret_cast<const uint4*>(g_feat16);
    // row r: uint4 index r*8 + g  (8 halves = dims [8g, 8g+8))

    float denom = 0.0f;
    float A0 = 0.f, A1 = 0.f, A2 = 0.f, A3 = 0.f;
    float A4 = 0.f, A5 = 0.f, A6 = 0.f, A7 = 0.f;

    // prologue: index for quad 0 and quad 1; row data for quad 0
    int s_cur = (nfull > 0) ? g_esrc[beg + grp] : 0;
    int s_nx  = (nfull > 1) ? g_esrc[beg + 4 + grp] : 0;
    uint4  h_n = make_uint4(0, 0, 0, 0);
    float  iv_n = 0.0f;
    if (nfull > 0) {
        iv_n = g_invn[s_cur];
        h_n  = feat16[(size_t)s_cur * 8 + g];
    }

    for (int it = 0; it < nfull; it++) {
        uint4 h = h_n;
        float iv = iv_n;
        s_cur = s_nx;                           // index for it+1 (arrived)
        if (it + 2 < nfull)                     // index prefetch, depth 2
            s_nx = g_esrc[beg + (it + 2) * 4 + grp];
        if (it + 1 < nfull) {                   // row prefetch, depth 1
            iv_n = g_invn[s_cur];
            h_n  = feat16[(size_t)s_cur * 8 + g];
        }
        float2 f0 = __half22float2(*reinterpret_cast<__half2*>(&h.x));
        float2 f1 = __half22float2(*reinterpret_cast<__half2*>(&h.y));
        float2 f2 = __half22float2(*reinterpret_cast<__half2*>(&h.z));
        float2 f3 = __half22float2(*reinterpret_cast<__half2*>(&h.w));
        float p = f0.x * fd0.x + f0.y * fd0.y + f1.x * fd0.z + f1.y * fd0.w
                + f2.x * fd1.x + f2.y * fd1.y + f3.x * fd1.z + f3.y * fd1.w;
        p += __shfl_xor_sync(0xffffffffu, p, 4);
        p += __shfl_xor_sync(0xffffffffu, p, 2);
        p += __shfl_xor_sync(0xffffffffu, p, 1);
        float ex = __expf(bscale * iv * p);
        denom += ex;
        A0 += ex * f0.x; A1 += ex * f0.y; A2 += ex * f1.x; A3 += ex * f1.y;
        A4 += ex * f2.x; A5 += ex * f2.y; A6 += ex * f3.x; A7 += ex * f3.y;
    }
    if (rem) {                              // tail quad, predicated once
        int e = beg + nfull * 4 + grp;
        bool valid = (grp < rem);
        int s = valid ? g_esrc[e] : 0;
        float iv = g_invn[s];
        uint4 h = feat16[(size_t)s * 8 + g];
        float2 f0 = __half22float2(*reinterpret_cast<__half2*>(&h.x));
        float2 f1 = __half22float2(*reinterpret_cast<__half2*>(&h.y));
        float2 f2 = __half22float2(*reinterpret_cast<__half2*>(&h.z));
        float2 f3 = __half22float2(*reinterpret_cast<__half2*>(&h.w));
        float p = f0.x * fd0.x + f0.y * fd0.y + f1.x * fd0.z + f1.y * fd0.w
                + f2.x * fd1.x + f2.y * fd1.y + f3.x * fd1.z + f3.y * fd1.w;
        p += __shfl_xor_sync(0xffffffffu, p, 4);
        p += __shfl_xor_sync(0xffffffffu, p, 2);
        p += __shfl_xor_sync(0xffffffffu, p, 1);
        float ex = valid ? __expf(bscale * iv * p) : 0.0f;
        denom += ex;
        A0 += ex * f0.x; A1 += ex * f0.y; A2 += ex * f1.x; A3 += ex * f1.y;
        A4 += ex * f2.x; A5 += ex * f2.y; A6 += ex * f3.x; A7 += ex * f3.y;
    }

    // combine the 4 edge-groups (lane g in each group owns the same dims)
    #pragma unroll
    for (int o = 8; o <= 16; o <<= 1) {
        denom += __shfl_xor_sync(0xffffffffu, denom, o);
        A0 += __shfl_xor_sync(0xffffffffu, A0, o);
        A1 += __shfl_xor_sync(0xffffffffu, A1, o);
        A2 += __shfl_xor_sync(0xffffffffu, A2, o);
        A3 += __shfl_xor_sync(0xffffffffu, A3, o);
        A4 += __shfl_xor_sync(0xffffffffu, A4, o);
        A5 += __shfl_xor_sync(0xffffffffu, A5, o);
        A6 += __shfl_xor_sync(0xffffffffu, A6, o);
        A7 += __shfl_xor_sync(0xffffffffu, A7, o);
    }

    if (lane < 8) {
        float r = 1.0f / fmaxf(denom, EPSV);
        float4 o1 = make_float4(A0 * r, A1 * r, A2 * r, A3 * r);
        float4 o2 = make_float4(A4 * r, A5 * r, A6 * r, A7 * r);
        float4* out4 = reinterpret_cast<float4*>(out);
        out4[(size_t)w * 16 + 2 * g]     = o1;
        out4[(size_t)w * 16 + 2 * g + 1] = o2;
    }
}

// ---------------------------------------------------------------------------
extern "C" void kernel_launch(void* const* d_in, const int* in_sizes, int n_in,
                              void* d_out, int out_size) {
    const float* feat = (const float*)d_in[0];
    const float* beta = (const float*)d_in[1];
    const int*   src  = (const int*)d_in[2];   // JAX default int32 (no x64)
    const int*   dst  = (const int*)d_in[3];
    float*       out  = (float*)d_out;

    int n_nodes = in_sizes[0] / D;
    int n_edges = in_sizes[2];
    if (n_nodes > NN_MAX) n_nodes = NN_MAX;
    if (n_edges > EE_MAX) n_edges = EE_MAX;

    const int T = 256;
    int roww_blocks = (n_nodes + 7) / 8;          // warp-per-row/dst
    int scat_blocks = (n_edges + T * 4 - 1) / (T * 4);
    int scan_blocks = (n_nodes + SCAN_B - 1) / SCAN_B;   // <= 128 required

    k_norm_hist<<<roww_blocks, T>>>(feat, dst, n_nodes, n_edges);
    k_scan     <<<scan_blocks, SCAN_B>>>(n_nodes, n_edges);
    k_scatter  <<<scat_blocks, T>>>(src, dst, n_edges);
    k_agg      <<<roww_blocks, T>>>(feat, beta, out, n_nodes);
}